// round 1
// baseline (speedup 1.0000x reference)
#include <cuda_runtime.h>
#include <math.h>
#include <stdint.h>

#define NTOK 8192
#define DDIM 1024
#define HDIM 4096
#define NEXP 8
#define NASSIGN (NTOK*2)

// ---------------- scratch (device globals; no allocation) ----------------
__device__ float g_h[(size_t)NASSIGN * HDIM];      // 268 MB: hidden activations per assignment
__device__ float g_outb[(size_t)NASSIGN * DDIM];   // 67 MB: expert outputs per assignment
__device__ float g_loadc[NTOK * NEXP];             // per-token load contributions
__device__ int   g_route_e[NASSIGN];
__device__ float g_route_g[NASSIGN];
__device__ int   g_counts[NEXP];
__device__ int   g_perm[NEXP * NTOK];              // assignment ids grouped by expert
__device__ float g_load[NEXP];
__device__ float g_imp[NEXP];

// ---------------- helpers ----------------
__device__ __forceinline__ unsigned long long pack_dup(float a) {
    unsigned long long r;
    asm("mov.b64 %0, {%1, %1};" : "=l"(r) : "f"(a));
    return r;
}
__device__ __forceinline__ unsigned long long fma2(unsigned long long a,
                                                   unsigned long long b,
                                                   unsigned long long c) {
    unsigned long long d;
    asm("fma.rn.f32x2 %0, %1, %2, %3;" : "=l"(d) : "l"(a), "l"(b), "l"(c));
    return d;
}
__device__ __forceinline__ float2 unpack2(unsigned long long v) {
    float2 r;
    asm("mov.b64 {%0, %1}, %2;" : "=f"(r.x), "=f"(r.y) : "l"(v));
    return r;
}
union F4U { float4 v; unsigned long long u[2]; float f[4]; };

// ---------------- zero counters ----------------
__global__ void zero_kernel() {
    if (threadIdx.x < NEXP) g_counts[threadIdx.x] = 0;
}

// ---------------- gating: logits, top-k, routing, load contribs ----------------
__global__ void gate_kernel(const float* __restrict__ x,
                            const float* __restrict__ noise,
                            const float* __restrict__ wg,
                            const float* __restrict__ wn) {
    int warp = threadIdx.x >> 5;
    int lane = threadIdx.x & 31;
    int n = blockIdx.x * 8 + warp;
    if (n >= NTOK) return;

    float ac[8] = {0,0,0,0,0,0,0,0};
    float an[8] = {0,0,0,0,0,0,0,0};
    const float* xr = x + (size_t)n * DDIM;
    for (int d = lane; d < DDIM; d += 32) {
        float xv = xr[d];
        const float4* wgp = (const float4*)(wg + (size_t)d * 8);
        const float4* wnp = (const float4*)(wn + (size_t)d * 8);
        float4 gA = wgp[0], gB = wgp[1];
        float4 nA = wnp[0], nB = wnp[1];
        ac[0] += xv * gA.x; ac[1] += xv * gA.y; ac[2] += xv * gA.z; ac[3] += xv * gA.w;
        ac[4] += xv * gB.x; ac[5] += xv * gB.y; ac[6] += xv * gB.z; ac[7] += xv * gB.w;
        an[0] += xv * nA.x; an[1] += xv * nA.y; an[2] += xv * nA.z; an[3] += xv * nA.w;
        an[4] += xv * nB.x; an[5] += xv * nB.y; an[6] += xv * nB.z; an[7] += xv * nB.w;
    }
    #pragma unroll
    for (int off = 16; off; off >>= 1) {
        #pragma unroll
        for (int e = 0; e < 8; e++) {
            ac[e] += __shfl_xor_sync(0xffffffffu, ac[e], off);
            an[e] += __shfl_xor_sync(0xffffffffu, an[e], off);
        }
    }
    if (lane == 0) {
        float clean[8], sd[8], nz[8];
        #pragma unroll
        for (int e = 0; e < 8; e++) {
            clean[e] = ac[e];
            float z = an[e];
            float sp = fmaxf(z, 0.0f) + log1pf(expf(-fabsf(z)));  // stable softplus
            sd[e] = sp + 0.01f;
            nz[e] = clean[e] + noise[(size_t)n * 8 + e] * sd[e];
        }
        // top-3 (values), top-2 (indices); strict > matches jax lowest-index tie-break
        int i0 = 0, i1 = -1;
        float v0 = nz[0], v1 = -INFINITY, v2 = -INFINITY;
        #pragma unroll
        for (int e = 1; e < 8; e++) {
            float v = nz[e];
            if (v > v0)      { v2 = v1; v1 = v0; i1 = i0; v0 = v; i0 = e; }
            else if (v > v1) { v2 = v1; v1 = v;  i1 = e; }
            else if (v > v2) { v2 = v; }
        }
        float t = expf(v1 - v0);
        float gate0 = 1.0f / (1.0f + t);
        float gate1 = t / (1.0f + t);
        #pragma unroll
        for (int e = 0; e < 8; e++) {
            bool is_in = nz[e] > v2;          // thr_in = 3rd value
            float thr = is_in ? v2 : v1;       // thr_out = 2nd value
            g_loadc[(size_t)n * 8 + e] = normcdff((clean[e] - thr) / sd[e]);
        }
        g_route_e[2 * n]     = i0;  g_route_g[2 * n]     = gate0;
        g_route_e[2 * n + 1] = i1;  g_route_g[2 * n + 1] = gate1;
        int p0 = atomicAdd(&g_counts[i0], 1);
        g_perm[i0 * NTOK + p0] = 2 * n;
        int p1 = atomicAdd(&g_counts[i1], 1);
        g_perm[i1 * NTOK + p1] = 2 * n + 1;
    }
}

// ---------------- deterministic reductions for load / importance ----------------
__global__ void reduce_kernel() {
    int e = blockIdx.x;
    int t = threadIdx.x;
    float sl = 0.0f, si = 0.0f;
    for (int n = t; n < NTOK; n += 256) sl += g_loadc[(size_t)n * 8 + e];
    for (int a = t; a < NASSIGN; a += 256)
        if (g_route_e[a] == e) si += g_route_g[a];
    __shared__ float shl[256], shi[256];
    shl[t] = sl; shi[t] = si;
    __syncthreads();
    for (int off = 128; off; off >>= 1) {
        if (t < off) { shl[t] += shl[t + off]; shi[t] += shi[t + off]; }
        __syncthreads();
    }
    if (t == 0) { g_load[e] = shl[0]; g_imp[e] = shi[0]; }
}

__global__ void loss_kernel(float* __restrict__ out) {
    if (threadIdx.x != 0 || blockIdx.x != 0) return;
    float mi = 0.0f, ml = 0.0f;
    for (int e = 0; e < NEXP; e++) { mi += g_imp[e]; ml += g_load[e]; }
    mi *= (1.0f / NEXP); ml *= (1.0f / NEXP);
    float vi = 0.0f, vl = 0.0f;
    for (int e = 0; e < NEXP; e++) {
        float di = g_imp[e] - mi;  vi += di * di;
        float dl = g_load[e] - ml; vl += dl * dl;
    }
    vi *= (1.0f / (NEXP - 1)); vl *= (1.0f / (NEXP - 1));
    out[0] = (vi / (mi * mi + 1e-10f) + vl / (ml * ml + 1e-10f)) * 0.01f;
}

// ---------------- grouped expert GEMM ----------------
// WHICH==0: h = relu(x[token] @ W1[e] + b1[e]), K=1024, Ncols=4096
// WHICH==1: out = h @ W2[e] + b2[e],            K=4096, Ncols=1024
template <int WHICH>
__global__ __launch_bounds__(128) void moe_gemm(const float* __restrict__ X,
                                                const float* __restrict__ B,
                                                const float* __restrict__ bias) {
    constexpr int KD = WHICH ? HDIM : DDIM;
    constexpr int NC = WHICH ? DDIM : HDIM;

    int e = blockIdx.z;
    int count = g_counts[e];
    int m0 = blockIdx.y * 64;
    if (m0 >= count) return;
    int c0 = blockIdx.x * 128;

    const float* Be = B + (size_t)e * KD * NC;
    const float* biase = bias + (size_t)e * NC;

    __shared__ float As[16][68];
    __shared__ float Bs[16][132];
    __shared__ int s_a[64];

    int t = threadIdx.x;
    if (t < 64) {
        int m = m0 + t;
        s_a[t] = (m < count) ? g_perm[e * NTOK + m] : -1;
    }
    __syncthreads();

    int ty = t >> 4, tx = t & 15;
    int row = t >> 1, kv = t & 1;
    int arow = s_a[row];
    const float* Arow = nullptr;
    if (arow >= 0) {
        if (WHICH == 0) Arow = X + (size_t)(arow >> 1) * DDIM;
        else            Arow = g_h + (size_t)arow * HDIM;
    }

    unsigned long long acc[8][4];
    #pragma unroll
    for (int i = 0; i < 8; i++)
        #pragma unroll
        for (int j = 0; j < 4; j++) acc[i][j] = 0ull;

    int bkk[4], bc4[4];
    #pragma unroll
    for (int i = 0; i < 4; i++) {
        int idx = t + i * 128;
        bkk[i] = idx >> 5;
        bc4[i] = idx & 31;
    }

    for (int k0 = 0; k0 < KD; k0 += 16) {
        float4 av0, av1;
        if (Arow) {
            av0 = *(const float4*)(Arow + k0 + kv * 8);
            av1 = *(const float4*)(Arow + k0 + kv * 8 + 4);
        } else {
            av0 = make_float4(0.f, 0.f, 0.f, 0.f);
            av1 = av0;
        }
        float4 bv[4];
        #pragma unroll
        for (int i = 0; i < 4; i++)
            bv[i] = *(const float4*)(Be + (size_t)(k0 + bkk[i]) * NC + c0 + bc4[i] * 4);

        __syncthreads();  // previous compute done before overwriting smem
        int kb = kv * 8;
        As[kb + 0][row] = av0.x; As[kb + 1][row] = av0.y;
        As[kb + 2][row] = av0.z; As[kb + 3][row] = av0.w;
        As[kb + 4][row] = av1.x; As[kb + 5][row] = av1.y;
        As[kb + 6][row] = av1.z; As[kb + 7][row] = av1.w;
        #pragma unroll
        for (int i = 0; i < 4; i++)
            *(float4*)&Bs[bkk[i]][bc4[i] * 4] = bv[i];
        __syncthreads();

        #pragma unroll
        for (int kk = 0; kk < 16; kk++) {
            float4 a0 = *(const float4*)&As[kk][ty * 8];
            float4 a1 = *(const float4*)&As[kk][ty * 8 + 4];
            F4U b0, b1;
            b0.v = *(const float4*)&Bs[kk][tx * 8];
            b1.v = *(const float4*)&Bs[kk][tx * 8 + 4];
            unsigned long long bb[4] = { b0.u[0], b0.u[1], b1.u[0], b1.u[1] };
            float aa[8] = { a0.x, a0.y, a0.z, a0.w, a1.x, a1.y, a1.z, a1.w };
            #pragma unroll
            for (int i = 0; i < 8; i++) {
                unsigned long long ad = pack_dup(aa[i]);
                #pragma unroll
                for (int j = 0; j < 4; j++) acc[i][j] = fma2(ad, bb[j], acc[i][j]);
            }
        }
    }

    F4U bia0, bia1;
    bia0.v = *(const float4*)(biase + c0 + tx * 8);
    bia1.v = *(const float4*)(biase + c0 + tx * 8 + 4);
    float bb8[8] = { bia0.f[0], bia0.f[1], bia0.f[2], bia0.f[3],
                     bia1.f[0], bia1.f[1], bia1.f[2], bia1.f[3] };

    #pragma unroll
    for (int i = 0; i < 8; i++) {
        int m = m0 + ty * 8 + i;
        if (m < count) {
            int a = s_a[ty * 8 + i];
            float* Crow;
            if (WHICH == 0) Crow = g_h   + (size_t)a * NC + c0 + tx * 8;
            else            Crow = g_outb + (size_t)a * NC + c0 + tx * 8;
            F4U o0, o1;
            #pragma unroll
            for (int j = 0; j < 4; j++) {
                float2 p = unpack2(acc[i][j]);
                float v0 = p.x + bb8[2 * j];
                float v1 = p.y + bb8[2 * j + 1];
                if (WHICH == 0) { v0 = fmaxf(v0, 0.0f); v1 = fmaxf(v1, 0.0f); }
                if (j < 2) { o0.f[2 * j] = v0; o0.f[2 * j + 1] = v1; }
                else       { o1.f[2 * (j - 2)] = v0; o1.f[2 * (j - 2) + 1] = v1; }
            }
            *(float4*)Crow = o0.v;
            *(float4*)(Crow + 4) = o1.v;
        }
    }
}

// ---------------- combine: y[n] = g0*out[2n] + g1*out[2n+1] ----------------
__global__ void combine_kernel(float* __restrict__ y) {
    int n = blockIdx.x;
    int t = threadIdx.x;
    float gate0 = g_route_g[2 * n];
    float gate1 = g_route_g[2 * n + 1];
    const float4* o0 = (const float4*)(g_outb + (size_t)(2 * n) * DDIM);
    const float4* o1 = (const float4*)(g_outb + (size_t)(2 * n + 1) * DDIM);
    float4* yp = (float4*)(y + (size_t)n * DDIM);
    float4 a = o0[t], b = o1[t];
    yp[t] = make_float4(gate0 * a.x + gate1 * b.x,
                        gate0 * a.y + gate1 * b.y,
                        gate0 * a.z + gate1 * b.z,
                        gate0 * a.w + gate1 * b.w);
}

// ---------------- launch ----------------
extern "C" void kernel_launch(void* const* d_in, const int* in_sizes, int n_in,
                              void* d_out, int out_size) {
    (void)in_sizes; (void)n_in; (void)out_size;
    const float* x  = (const float*)d_in[0];
    const float* nz = (const float*)d_in[1];
    const float* wg = (const float*)d_in[2];
    const float* wn = (const float*)d_in[3];
    const float* W1 = (const float*)d_in[4];
    const float* b1 = (const float*)d_in[5];
    const float* W2 = (const float*)d_in[6];
    const float* b2 = (const float*)d_in[7];
    float* y = (float*)d_out;

    zero_kernel<<<1, 32>>>();
    gate_kernel<<<NTOK / 8, 256>>>(x, nz, wg, wn);
    reduce_kernel<<<NEXP, 256>>>();
    loss_kernel<<<1, 1>>>(y + (size_t)NTOK * DDIM);
    moe_gemm<0><<<dim3(HDIM / 128, NTOK / 64, NEXP), 128>>>(x, W1, b1);
    moe_gemm<1><<<dim3(DDIM / 128, NTOK / 64, NEXP), 128>>>(x, W2, b2);
    combine_kernel<<<NTOK, 256>>>(y);
}

// round 4
// speedup vs baseline: 2.4873x; 2.4873x over previous
#include <cuda_runtime.h>
#include <cuda_bf16.h>
#include <math.h>
#include <stdint.h>

#define NTOK 8192
#define DDIM 1024
#define HDIM 4096
#define NEXP 8
#define NASSIGN (NTOK*2)

// ---------------- scratch (device globals; no allocation) ----------------
__device__ float g_outb[(size_t)NASSIGN * DDIM];
__device__ float g_loadc[NTOK * NEXP];
__device__ int   g_route_e[NASSIGN];
__device__ float g_route_g[NASSIGN];
__device__ int   g_counts[NEXP];
__device__ int   g_perm[NEXP * NTOK];
__device__ float g_load[NEXP];
__device__ float g_imp[NEXP];
// bf16 hi/lo splits (same layout as source: x [N][D], W [E][K][N], h [NASSIGN][H])
__device__ __nv_bfloat16 g_x_hi[(size_t)NTOK * DDIM];
__device__ __nv_bfloat16 g_x_lo[(size_t)NTOK * DDIM];
__device__ __nv_bfloat16 g_h_hi[(size_t)NASSIGN * HDIM];
__device__ __nv_bfloat16 g_h_lo[(size_t)NASSIGN * HDIM];
__device__ __nv_bfloat16 g_w1_hi[(size_t)NEXP * DDIM * HDIM];
__device__ __nv_bfloat16 g_w1_lo[(size_t)NEXP * DDIM * HDIM];
__device__ __nv_bfloat16 g_w2_hi[(size_t)NEXP * HDIM * DDIM];
__device__ __nv_bfloat16 g_w2_lo[(size_t)NEXP * HDIM * DDIM];

// ---------------- helpers ----------------
__device__ __forceinline__ uint32_t smem_to_u32(const void* p) {
    uint32_t a;
    asm("{ .reg .u64 t; cvta.to.shared.u64 t, %1; cvt.u32.u64 %0, t; }" : "=r"(a) : "l"(p));
    return a;
}
__device__ __forceinline__ void ldsm4(uint32_t* r, uint32_t a) {
    asm volatile("ldmatrix.sync.aligned.m8n8.x4.shared.b16 {%0,%1,%2,%3}, [%4];"
        : "=r"(r[0]), "=r"(r[1]), "=r"(r[2]), "=r"(r[3]) : "r"(a));
}
__device__ __forceinline__ void ldsm4t(uint32_t* r, uint32_t a) {
    asm volatile("ldmatrix.sync.aligned.m8n8.x4.trans.shared.b16 {%0,%1,%2,%3}, [%4];"
        : "=r"(r[0]), "=r"(r[1]), "=r"(r[2]), "=r"(r[3]) : "r"(a));
}
__device__ __forceinline__ void mma16816(float* c, const uint32_t* a, const uint32_t* b) {
    asm volatile("mma.sync.aligned.m16n8k16.row.col.f32.bf16.bf16.f32 "
        "{%0,%1,%2,%3}, {%4,%5,%6,%7}, {%8,%9}, {%0,%1,%2,%3};"
        : "+f"(c[0]), "+f"(c[1]), "+f"(c[2]), "+f"(c[3])
        : "r"(a[0]), "r"(a[1]), "r"(a[2]), "r"(a[3]), "r"(b[0]), "r"(b[1]));
}
#define CP_ASYNC16(dst, src, sz) \
    asm volatile("cp.async.cg.shared.global [%0], [%1], 16, %2;" \
        :: "r"(dst), "l"(src), "r"(sz) : "memory")
#define CP_COMMIT() asm volatile("cp.async.commit_group;" ::: "memory")
#define CP_WAIT1()  asm volatile("cp.async.wait_group 1;" ::: "memory")
#define CP_WAIT0()  asm volatile("cp.async.wait_group 0;" ::: "memory")

__device__ __forceinline__ uint32_t pack_bf16x2(float x, float y) {
    __nv_bfloat162 h = __floats2bfloat162_rn(x, y);
    uint32_t u; memcpy(&u, &h, 4); return u;
}

// ---------------- zero counters ----------------
__global__ void zero_kernel() {
    if (threadIdx.x < NEXP) g_counts[threadIdx.x] = 0;
}

// ---------------- gating ----------------
__global__ void gate_kernel(const float* __restrict__ x,
                            const float* __restrict__ noise,
                            const float* __restrict__ wg,
                            const float* __restrict__ wn) {
    int warp = threadIdx.x >> 5;
    int lane = threadIdx.x & 31;
    int n = blockIdx.x * 8 + warp;
    if (n >= NTOK) return;
    float ac[8] = {0,0,0,0,0,0,0,0};
    float an[8] = {0,0,0,0,0,0,0,0};
    const float* xr = x + (size_t)n * DDIM;
    for (int d = lane; d < DDIM; d += 32) {
        float xv = xr[d];
        const float4* wgp = (const float4*)(wg + (size_t)d * 8);
        const float4* wnp = (const float4*)(wn + (size_t)d * 8);
        float4 gA = wgp[0], gB = wgp[1];
        float4 nA = wnp[0], nB = wnp[1];
        ac[0] += xv * gA.x; ac[1] += xv * gA.y; ac[2] += xv * gA.z; ac[3] += xv * gA.w;
        ac[4] += xv * gB.x; ac[5] += xv * gB.y; ac[6] += xv * gB.z; ac[7] += xv * gB.w;
        an[0] += xv * nA.x; an[1] += xv * nA.y; an[2] += xv * nA.z; an[3] += xv * nA.w;
        an[4] += xv * nB.x; an[5] += xv * nB.y; an[6] += xv * nB.z; an[7] += xv * nB.w;
    }
    #pragma unroll
    for (int off = 16; off; off >>= 1)
        #pragma unroll
        for (int e = 0; e < 8; e++) {
            ac[e] += __shfl_xor_sync(0xffffffffu, ac[e], off);
            an[e] += __shfl_xor_sync(0xffffffffu, an[e], off);
        }
    if (lane == 0) {
        float clean[8], sd[8], nz[8];
        #pragma unroll
        for (int e = 0; e < 8; e++) {
            clean[e] = ac[e];
            float z = an[e];
            float sp = fmaxf(z, 0.0f) + log1pf(expf(-fabsf(z)));
            sd[e] = sp + 0.01f;
            nz[e] = clean[e] + noise[(size_t)n * 8 + e] * sd[e];
        }
        int i0 = 0, i1 = -1;
        float v0 = nz[0], v1 = -INFINITY, v2 = -INFINITY;
        #pragma unroll
        for (int e = 1; e < 8; e++) {
            float v = nz[e];
            if (v > v0)      { v2 = v1; v1 = v0; i1 = i0; v0 = v; i0 = e; }
            else if (v > v1) { v2 = v1; v1 = v;  i1 = e; }
            else if (v > v2) { v2 = v; }
        }
        float t = expf(v1 - v0);
        float gate0 = 1.0f / (1.0f + t);
        float gate1 = t / (1.0f + t);
        #pragma unroll
        for (int e = 0; e < 8; e++) {
            bool is_in = nz[e] > v2;
            float thr = is_in ? v2 : v1;
            g_loadc[(size_t)n * 8 + e] = normcdff((clean[e] - thr) / sd[e]);
        }
        g_route_e[2 * n]     = i0;  g_route_g[2 * n]     = gate0;
        g_route_e[2 * n + 1] = i1;  g_route_g[2 * n + 1] = gate1;
        int p0 = atomicAdd(&g_counts[i0], 1);
        g_perm[i0 * NTOK + p0] = 2 * n;
        int p1 = atomicAdd(&g_counts[i1], 1);
        g_perm[i1 * NTOK + p1] = 2 * n + 1;
    }
}

__global__ void reduce_kernel() {
    int e = blockIdx.x;
    int t = threadIdx.x;
    float sl = 0.0f, si = 0.0f;
    for (int n = t; n < NTOK; n += 256) sl += g_loadc[(size_t)n * 8 + e];
    for (int a = t; a < NASSIGN; a += 256)
        if (g_route_e[a] == e) si += g_route_g[a];
    __shared__ float shl[256], shi[256];
    shl[t] = sl; shi[t] = si;
    __syncthreads();
    for (int off = 128; off; off >>= 1) {
        if (t < off) { shl[t] += shl[t + off]; shi[t] += shi[t + off]; }
        __syncthreads();
    }
    if (t == 0) { g_load[e] = shl[0]; g_imp[e] = shi[0]; }
}

__global__ void loss_kernel(float* __restrict__ out) {
    if (threadIdx.x != 0 || blockIdx.x != 0) return;
    float mi = 0.0f, ml = 0.0f;
    for (int e = 0; e < NEXP; e++) { mi += g_imp[e]; ml += g_load[e]; }
    mi *= (1.0f / NEXP); ml *= (1.0f / NEXP);
    float vi = 0.0f, vl = 0.0f;
    for (int e = 0; e < NEXP; e++) {
        float di = g_imp[e] - mi;  vi += di * di;
        float dl = g_load[e] - ml; vl += dl * dl;
    }
    vi *= (1.0f / (NEXP - 1)); vl *= (1.0f / (NEXP - 1));
    out[0] = (vi / (mi * mi + 1e-10f) + vl / (ml * ml + 1e-10f)) * 0.01f;
}

// ---------------- elementwise fp32 -> bf16 hi/lo split ----------------
__global__ void convert_split(const float4* __restrict__ src,
                              uint32_t* __restrict__ hi, uint32_t* __restrict__ lo,
                              size_t n4) {
    size_t stride = (size_t)gridDim.x * blockDim.x;
    for (size_t i = (size_t)blockIdx.x * blockDim.x + threadIdx.x; i < n4; i += stride) {
        float4 v = src[i];
        __nv_bfloat16 h0 = __float2bfloat16(v.x), h1 = __float2bfloat16(v.y);
        __nv_bfloat16 h2 = __float2bfloat16(v.z), h3 = __float2bfloat16(v.w);
        hi[i * 2 + 0] = pack_bf16x2(v.x, v.y);
        hi[i * 2 + 1] = pack_bf16x2(v.z, v.w);
        lo[i * 2 + 0] = pack_bf16x2(v.x - __bfloat162float(h0), v.y - __bfloat162float(h1));
        lo[i * 2 + 1] = pack_bf16x2(v.z - __bfloat162float(h2), v.w - __bfloat162float(h3));
    }
}

// ---------------- grouped expert GEMM via mma.sync (bf16 hi/lo, 3 terms) --------
// WHICH==0: h = relu(x @ W1[e] + b1[e]),  K=1024, NC=4096, out -> g_h hi/lo bf16
// WHICH==1: out = h @ W2[e] + b2[e],      K=4096, NC=1024, out -> g_outb fp32
// CTA tile 128x128, k-chunk 32, 8 warps (2m x 4n), warp tile 64x32.
#define STAGE_BYTES 32768
#define GEMM_SMEM (2 * STAGE_BYTES)

template <int WHICH>
__global__ __launch_bounds__(256, 1) void moe_gemm_mma(const float* __restrict__ bias) {
    constexpr int KD = WHICH ? HDIM : DDIM;
    constexpr int NC = WHICH ? DDIM : HDIM;
    constexpr int NST = KD / 32;

    const int e = blockIdx.z;
    const int count = g_counts[e];
    const int m0 = blockIdx.y * 128;
    if (m0 >= count) return;
    const int c0 = blockIdx.x * 128;

    extern __shared__ char smem[];
    __shared__ int s_a[128];
    const uint32_t sb = smem_to_u32(smem);
    const int t = threadIdx.x;
    const int lane = t & 31, wid = t >> 5;
    const int wm = wid & 1, wn = wid >> 1;

    if (t < 128) {
        int m = m0 + t;
        s_a[t] = (m < count) ? g_perm[e * NTOK + m] : -1;
    }
    __syncthreads();

    // ---- per-thread cp.async source/dest precompute ----
    const __nv_bfloat16* Ahi_b = WHICH ? g_h_hi : g_x_hi;
    const __nv_bfloat16* Alo_b = WHICH ? g_h_lo : g_x_lo;
    const __nv_bfloat16* Whi_b = (WHICH ? g_w2_hi : g_w1_hi) + (size_t)e * KD * NC + c0;
    const __nv_bfloat16* Wlo_b = (WHICH ? g_w2_lo : g_w1_lo) + (size_t)e * KD * NC + c0;

    const __nv_bfloat16 *srcAh[2], *srcAl[2];
    uint32_t adst[2]; int asz[2];
    #pragma unroll
    for (int i = 0; i < 2; i++) {
        int r = (t >> 2) + 64 * i, ca = t & 3;
        int a = s_a[r];
        int row = (a < 0) ? 0 : (WHICH ? a : (a >> 1));
        srcAh[i] = Ahi_b + (size_t)row * KD + ca * 8;
        srcAl[i] = Alo_b + (size_t)row * KD + ca * 8;
        asz[i] = (a < 0) ? 0 : 16;
        adst[i] = r * 64 + ((ca ^ ((r >> 1) & 3)) << 4);
    }
    const __nv_bfloat16 *srcBh[2], *srcBl[2];
    uint32_t bdst[2];
    #pragma unroll
    for (int i = 0; i < 2; i++) {
        int r = (t >> 4) + 16 * i, cb = t & 15;
        srcBh[i] = Whi_b + (size_t)r * NC + cb * 8;
        srcBl[i] = Wlo_b + (size_t)r * NC + cb * 8;
        bdst[i] = r * 256 + ((cb ^ (r & 7)) << 4);
    }

    auto load_stage = [&](int s) {
        uint32_t base = sb + (uint32_t)(s & 1) * STAGE_BYTES;
        int koff = s * 32;
        size_t bkoff = (size_t)koff * NC;
        #pragma unroll
        for (int i = 0; i < 2; i++) {
            CP_ASYNC16(base + adst[i],          srcAh[i] + koff, asz[i]);
            CP_ASYNC16(base + 8192u + adst[i],  srcAl[i] + koff, asz[i]);
        }
        #pragma unroll
        for (int i = 0; i < 2; i++) {
            CP_ASYNC16(base + 16384u + bdst[i], srcBh[i] + bkoff, 16);
            CP_ASYNC16(base + 24576u + bdst[i], srcBl[i] + bkoff, 16);
        }
        CP_COMMIT();
    };

    // ---- per-lane ldmatrix offsets ----
    uint32_t aoff[4][2], boff[2][2];
    #pragma unroll
    for (int mi = 0; mi < 4; mi++) {
        int r = wm * 64 + mi * 16 + (lane & 15);
        #pragma unroll
        for (int ks = 0; ks < 2; ks++) {
            int ca = ks * 2 + (lane >> 4);
            aoff[mi][ks] = r * 64 + ((ca ^ ((r >> 1) & 3)) << 4);
        }
    }
    #pragma unroll
    for (int nj = 0; nj < 2; nj++) {
        #pragma unroll
        for (int ks = 0; ks < 2; ks++) {
            int r = ks * 16 + (lane & 15);
            int cb = wn * 4 + nj * 2 + (lane >> 4);
            boff[nj][ks] = r * 256 + ((cb ^ (r & 7)) << 4);
        }
    }

    float acc[4][4][4];
    #pragma unroll
    for (int i = 0; i < 4; i++)
        #pragma unroll
        for (int j = 0; j < 4; j++)
            #pragma unroll
            for (int k = 0; k < 4; k++) acc[i][j][k] = 0.0f;

    load_stage(0);
    load_stage(1);

    for (int s = 0; s < NST; s++) {
        if (s == NST - 1) { CP_WAIT0(); } else { CP_WAIT1(); }
        __syncthreads();
        uint32_t ab = sb + (uint32_t)(s & 1) * STAGE_BYTES;
        uint32_t bb = ab + 16384u;
        #pragma unroll
        for (int ks = 0; ks < 2; ks++) {
            uint32_t Ah[4][4], Al[4][4], Bh[2][4], Bl[2][4];
            #pragma unroll
            for (int mi = 0; mi < 4; mi++) {
                ldsm4(Ah[mi], ab + aoff[mi][ks]);
                ldsm4(Al[mi], ab + 8192u + aoff[mi][ks]);
            }
            #pragma unroll
            for (int nj = 0; nj < 2; nj++) {
                ldsm4t(Bh[nj], bb + boff[nj][ks]);
                ldsm4t(Bl[nj], bb + 8192u + boff[nj][ks]);
            }
            #pragma unroll
            for (int mi = 0; mi < 4; mi++) {
                #pragma unroll
                for (int n = 0; n < 4; n++) {
                    const uint32_t* bh = &Bh[n >> 1][(n & 1) * 2];
                    const uint32_t* bl = &Bl[n >> 1][(n & 1) * 2];
                    mma16816(acc[mi][n], Ah[mi], bh);
                    mma16816(acc[mi][n], Ah[mi], bl);
                    mma16816(acc[mi][n], Al[mi], bh);
                }
            }
        }
        if (s + 2 < NST) {
            __syncthreads();
            load_stage(s + 2);
        }
    }

    // ---- epilogue ----
    const float* bias_e = bias + (size_t)e * NC + c0;
    int colb = wn * 32 + (lane & 3) * 2;
    float2 bv[4];
    #pragma unroll
    for (int n = 0; n < 4; n++) bv[n] = *(const float2*)(bias_e + colb + n * 8);

    #pragma unroll
    for (int mi = 0; mi < 4; mi++) {
        #pragma unroll
        for (int half = 0; half < 2; half++) {
            int r = wm * 64 + mi * 16 + (lane >> 2) + half * 8;
            int a = s_a[r];
            if (a >= 0) {
                #pragma unroll
                for (int n = 0; n < 4; n++) {
                    float v0 = acc[mi][n][half * 2 + 0] + bv[n].x;
                    float v1 = acc[mi][n][half * 2 + 1] + bv[n].y;
                    size_t col = (size_t)c0 + colb + n * 8;
                    if (WHICH == 0) {
                        v0 = fmaxf(v0, 0.0f); v1 = fmaxf(v1, 0.0f);
                        __nv_bfloat16 h0 = __float2bfloat16(v0);
                        __nv_bfloat16 h1 = __float2bfloat16(v1);
                        size_t o = (size_t)a * HDIM + col;
                        *(uint32_t*)(g_h_hi + o) = pack_bf16x2(v0, v1);
                        *(uint32_t*)(g_h_lo + o) =
                            pack_bf16x2(v0 - __bfloat162float(h0), v1 - __bfloat162float(h1));
                    } else {
                        *(float2*)(g_outb + (size_t)a * DDIM + col) = make_float2(v0, v1);
                    }
                }
            }
        }
    }
}

// ---------------- combine ----------------
__global__ void combine_kernel(float* __restrict__ y) {
    int n = blockIdx.x;
    int t = threadIdx.x;
    float gate0 = g_route_g[2 * n];
    float gate1 = g_route_g[2 * n + 1];
    const float4* o0 = (const float4*)(g_outb + (size_t)(2 * n) * DDIM);
    const float4* o1 = (const float4*)(g_outb + (size_t)(2 * n + 1) * DDIM);
    float4* yp = (float4*)(y + (size_t)n * DDIM);
    float4 a = o0[t], b = o1[t];
    yp[t] = make_float4(gate0 * a.x + gate1 * b.x,
                        gate0 * a.y + gate1 * b.y,
                        gate0 * a.z + gate1 * b.z,
                        gate0 * a.w + gate1 * b.w);
}

// ---------------- launch ----------------
extern "C" void kernel_launch(void* const* d_in, const int* in_sizes, int n_in,
                              void* d_out, int out_size) {
    (void)in_sizes; (void)n_in; (void)out_size;
    const float* x  = (const float*)d_in[0];
    const float* nz = (const float*)d_in[1];
    const float* wg = (const float*)d_in[2];
    const float* wn = (const float*)d_in[3];
    const float* W1 = (const float*)d_in[4];
    const float* b1 = (const float*)d_in[5];
    const float* W2 = (const float*)d_in[6];
    const float* b2 = (const float*)d_in[7];
    float* y = (float*)d_out;

    cudaFuncSetAttribute(moe_gemm_mma<0>, cudaFuncAttributeMaxDynamicSharedMemorySize, GEMM_SMEM);
    cudaFuncSetAttribute(moe_gemm_mma<1>, cudaFuncAttributeMaxDynamicSharedMemorySize, GEMM_SMEM);

    zero_kernel<<<1, 32>>>();
    gate_kernel<<<NTOK / 8, 256>>>(x, nz, wg, wn);
    reduce_kernel<<<NEXP, 256>>>();
    loss_kernel<<<1, 1>>>(y + (size_t)NTOK * DDIM);

    void *xh, *xl, *w1h, *w1l, *w2h, *w2l;
    cudaGetSymbolAddress(&xh, g_x_hi);  cudaGetSymbolAddress(&xl, g_x_lo);
    cudaGetSymbolAddress(&w1h, g_w1_hi); cudaGetSymbolAddress(&w1l, g_w1_lo);
    cudaGetSymbolAddress(&w2h, g_w2_hi); cudaGetSymbolAddress(&w2l, g_w2_lo);

    convert_split<<<1024, 256>>>((const float4*)x, (uint32_t*)xh, (uint32_t*)xl,
                                 (size_t)NTOK * DDIM / 4);
    convert_split<<<4096, 256>>>((const float4*)W1, (uint32_t*)w1h, (uint32_t*)w1l,
                                 (size_t)NEXP * DDIM * HDIM / 4);
    convert_split<<<4096, 256>>>((const float4*)W2, (uint32_t*)w2h, (uint32_t*)w2l,
                                 (size_t)NEXP * HDIM * DDIM / 4);

    moe_gemm_mma<0><<<dim3(HDIM / 128, NASSIGN / 128, NEXP), 256, GEMM_SMEM>>>(b1);
    moe_gemm_mma<1><<<dim3(DDIM / 128, NASSIGN / 128, NEXP), 256, GEMM_SMEM>>>(b2);
    combine_kernel<<<NTOK, 256>>>(y);
}

// round 5
// speedup vs baseline: 2.6936x; 1.0829x over previous
#include <cuda_runtime.h>
#include <cuda_bf16.h>
#include <math.h>
#include <stdint.h>

#define NTOK 8192
#define DDIM 1024
#define HDIM 4096
#define NEXP 8
#define NASSIGN (NTOK*2)

// ---------------- scratch (device globals; no allocation) ----------------
__device__ float g_outb[(size_t)NASSIGN * DDIM];
__device__ float g_loadc[NTOK * NEXP];
__device__ int   g_route_e[NASSIGN];
__device__ float g_route_g[NASSIGN];
__device__ int   g_counts[NEXP];
__device__ int   g_perm[NEXP * NTOK];
__device__ float g_load[NEXP];
__device__ float g_imp[NEXP];
__device__ __nv_bfloat16 g_x_hi[(size_t)NTOK * DDIM];
__device__ __nv_bfloat16 g_x_lo[(size_t)NTOK * DDIM];
__device__ __nv_bfloat16 g_h_hi[(size_t)NASSIGN * HDIM];
__device__ __nv_bfloat16 g_h_lo[(size_t)NASSIGN * HDIM];
__device__ __nv_bfloat16 g_w1_hi[(size_t)NEXP * DDIM * HDIM];
__device__ __nv_bfloat16 g_w1_lo[(size_t)NEXP * DDIM * HDIM];
__device__ __nv_bfloat16 g_w2_hi[(size_t)NEXP * HDIM * DDIM];
__device__ __nv_bfloat16 g_w2_lo[(size_t)NEXP * HDIM * DDIM];

// ---------------- helpers ----------------
__device__ __forceinline__ uint32_t smem_to_u32(const void* p) {
    uint32_t a;
    asm("{ .reg .u64 t; cvta.to.shared.u64 t, %1; cvt.u32.u64 %0, t; }" : "=r"(a) : "l"(p));
    return a;
}
__device__ __forceinline__ void ldsm4(uint32_t* r, uint32_t a) {
    asm volatile("ldmatrix.sync.aligned.m8n8.x4.shared.b16 {%0,%1,%2,%3}, [%4];"
        : "=r"(r[0]), "=r"(r[1]), "=r"(r[2]), "=r"(r[3]) : "r"(a));
}
__device__ __forceinline__ void ldsm4t(uint32_t* r, uint32_t a) {
    asm volatile("ldmatrix.sync.aligned.m8n8.x4.trans.shared.b16 {%0,%1,%2,%3}, [%4];"
        : "=r"(r[0]), "=r"(r[1]), "=r"(r[2]), "=r"(r[3]) : "r"(a));
}
__device__ __forceinline__ void mma16816(float* c, const uint32_t* a, const uint32_t* b) {
    asm volatile("mma.sync.aligned.m16n8k16.row.col.f32.bf16.bf16.f32 "
        "{%0,%1,%2,%3}, {%4,%5,%6,%7}, {%8,%9}, {%0,%1,%2,%3};"
        : "+f"(c[0]), "+f"(c[1]), "+f"(c[2]), "+f"(c[3])
        : "r"(a[0]), "r"(a[1]), "r"(a[2]), "r"(a[3]), "r"(b[0]), "r"(b[1]));
}
#define CP_ASYNC16(dst, src, sz) \
    asm volatile("cp.async.cg.shared.global [%0], [%1], 16, %2;" \
        :: "r"(dst), "l"(src), "r"(sz) : "memory")
#define CP_COMMIT() asm volatile("cp.async.commit_group;" ::: "memory")
#define CP_WAIT1()  asm volatile("cp.async.wait_group 1;" ::: "memory")

__device__ __forceinline__ uint32_t pack_bf16x2(float x, float y) {
    __nv_bfloat162 h = __floats2bfloat162_rn(x, y);
    uint32_t u; memcpy(&u, &h, 4); return u;
}

// ---------------- zero counters ----------------
__global__ void zero_kernel() {
    if (threadIdx.x < NEXP) g_counts[threadIdx.x] = 0;
}

// ---------------- gating ----------------
__global__ void gate_kernel(const float* __restrict__ x,
                            const float* __restrict__ noise,
                            const float* __restrict__ wg,
                            const float* __restrict__ wn) {
    int warp = threadIdx.x >> 5;
    int lane = threadIdx.x & 31;
    int n = blockIdx.x * 8 + warp;
    if (n >= NTOK) return;
    float ac[8] = {0,0,0,0,0,0,0,0};
    float an[8] = {0,0,0,0,0,0,0,0};
    const float* xr = x + (size_t)n * DDIM;
    for (int d = lane; d < DDIM; d += 32) {
        float xv = xr[d];
        const float4* wgp = (const float4*)(wg + (size_t)d * 8);
        const float4* wnp = (const float4*)(wn + (size_t)d * 8);
        float4 gA = wgp[0], gB = wgp[1];
        float4 nA = wnp[0], nB = wnp[1];
        ac[0] += xv * gA.x; ac[1] += xv * gA.y; ac[2] += xv * gA.z; ac[3] += xv * gA.w;
        ac[4] += xv * gB.x; ac[5] += xv * gB.y; ac[6] += xv * gB.z; ac[7] += xv * gB.w;
        an[0] += xv * nA.x; an[1] += xv * nA.y; an[2] += xv * nA.z; an[3] += xv * nA.w;
        an[4] += xv * nB.x; an[5] += xv * nB.y; an[6] += xv * nB.z; an[7] += xv * nB.w;
    }
    #pragma unroll
    for (int off = 16; off; off >>= 1)
        #pragma unroll
        for (int e = 0; e < 8; e++) {
            ac[e] += __shfl_xor_sync(0xffffffffu, ac[e], off);
            an[e] += __shfl_xor_sync(0xffffffffu, an[e], off);
        }
    if (lane == 0) {
        float clean[8], sd[8], nz[8];
        #pragma unroll
        for (int e = 0; e < 8; e++) {
            clean[e] = ac[e];
            float z = an[e];
            float sp = fmaxf(z, 0.0f) + log1pf(expf(-fabsf(z)));
            sd[e] = sp + 0.01f;
            nz[e] = clean[e] + noise[(size_t)n * 8 + e] * sd[e];
        }
        int i0 = 0, i1 = -1;
        float v0 = nz[0], v1 = -INFINITY, v2 = -INFINITY;
        #pragma unroll
        for (int e = 1; e < 8; e++) {
            float v = nz[e];
            if (v > v0)      { v2 = v1; v1 = v0; i1 = i0; v0 = v; i0 = e; }
            else if (v > v1) { v2 = v1; v1 = v;  i1 = e; }
            else if (v > v2) { v2 = v; }
        }
        float t = expf(v1 - v0);
        float gate0 = 1.0f / (1.0f + t);
        float gate1 = t / (1.0f + t);
        #pragma unroll
        for (int e = 0; e < 8; e++) {
            bool is_in = nz[e] > v2;
            float thr = is_in ? v2 : v1;
            g_loadc[(size_t)n * 8 + e] = normcdff((clean[e] - thr) / sd[e]);
        }
        g_route_e[2 * n]     = i0;  g_route_g[2 * n]     = gate0;
        g_route_e[2 * n + 1] = i1;  g_route_g[2 * n + 1] = gate1;
        int p0 = atomicAdd(&g_counts[i0], 1);
        g_perm[i0 * NTOK + p0] = 2 * n;
        int p1 = atomicAdd(&g_counts[i1], 1);
        g_perm[i1 * NTOK + p1] = 2 * n + 1;
    }
}

__global__ void reduce_kernel() {
    int e = blockIdx.x;
    int t = threadIdx.x;
    float sl = 0.0f, si = 0.0f;
    for (int n = t; n < NTOK; n += 256) sl += g_loadc[(size_t)n * 8 + e];
    for (int a = t; a < NASSIGN; a += 256)
        if (g_route_e[a] == e) si += g_route_g[a];
    __shared__ float shl[256], shi[256];
    shl[t] = sl; shi[t] = si;
    __syncthreads();
    for (int off = 128; off; off >>= 1) {
        if (t < off) { shl[t] += shl[t + off]; shi[t] += shi[t + off]; }
        __syncthreads();
    }
    if (t == 0) { g_load[e] = shl[0]; g_imp[e] = shi[0]; }
}

__global__ void loss_kernel(float* __restrict__ out) {
    if (threadIdx.x != 0 || blockIdx.x != 0) return;
    float mi = 0.0f, ml = 0.0f;
    for (int e = 0; e < NEXP; e++) { mi += g_imp[e]; ml += g_load[e]; }
    mi *= (1.0f / NEXP); ml *= (1.0f / NEXP);
    float vi = 0.0f, vl = 0.0f;
    for (int e = 0; e < NEXP; e++) {
        float di = g_imp[e] - mi;  vi += di * di;
        float dl = g_load[e] - ml; vl += dl * dl;
    }
    vi *= (1.0f / (NEXP - 1)); vl *= (1.0f / (NEXP - 1));
    out[0] = (vi / (mi * mi + 1e-10f) + vl / (ml * ml + 1e-10f)) * 0.01f;
}

// ---------------- elementwise fp32 -> bf16 hi/lo split ----------------
__global__ void convert_split(const float4* __restrict__ src,
                              uint32_t* __restrict__ hi, uint32_t* __restrict__ lo,
                              size_t n4) {
    size_t stride = (size_t)gridDim.x * blockDim.x;
    for (size_t i = (size_t)blockIdx.x * blockDim.x + threadIdx.x; i < n4; i += stride) {
        float4 v = src[i];
        __nv_bfloat16 h0 = __float2bfloat16(v.x), h1 = __float2bfloat16(v.y);
        __nv_bfloat16 h2 = __float2bfloat16(v.z), h3 = __float2bfloat16(v.w);
        hi[i * 2 + 0] = pack_bf16x2(v.x, v.y);
        hi[i * 2 + 1] = pack_bf16x2(v.z, v.w);
        lo[i * 2 + 0] = pack_bf16x2(v.x - __bfloat162float(h0), v.y - __bfloat162float(h1));
        lo[i * 2 + 1] = pack_bf16x2(v.z - __bfloat162float(h2), v.w - __bfloat162float(h3));
    }
}

// ---------------- grouped expert GEMM via mma.sync (bf16 hi/lo, 3 terms) --------
// CTA tile 128x256, k-chunk 32, 8 warps (2m x 4n), warp tile 64x64, 3-stage pipe.
// Stage layout: Ah@0 (8K) | Al@8192 | Bh@16384 (16K) | Bl@32768 (16K) = 48K.
#define STAGE_BYTES 49152
#define NSTAGE 3
#define GEMM_SMEM (NSTAGE * STAGE_BYTES)

template <int WHICH>
__global__ __launch_bounds__(256, 1) void moe_gemm_mma(const float* __restrict__ bias) {
    constexpr int KD = WHICH ? HDIM : DDIM;
    constexpr int NC = WHICH ? DDIM : HDIM;
    constexpr int NST = KD / 32;

    const int e = blockIdx.z;
    const int count = g_counts[e];
    const int m0 = blockIdx.y * 128;
    if (m0 >= count) return;
    const int c0 = blockIdx.x * 256;

    extern __shared__ char smem[];
    __shared__ int s_a[128];
    const uint32_t sb = smem_to_u32(smem);
    const int t = threadIdx.x;
    const int lane = t & 31, wid = t >> 5;
    const int wm = wid & 1, wn = wid >> 1;

    if (t < 128) {
        int m = m0 + t;
        s_a[t] = (m < count) ? g_perm[e * NTOK + m] : -1;
    }
    __syncthreads();

    const __nv_bfloat16* Ahi_b = WHICH ? g_h_hi : g_x_hi;
    const __nv_bfloat16* Alo_b = WHICH ? g_h_lo : g_x_lo;
    const __nv_bfloat16* Whi_b = (WHICH ? g_w2_hi : g_w1_hi) + (size_t)e * KD * NC + c0;
    const __nv_bfloat16* Wlo_b = (WHICH ? g_w2_lo : g_w1_lo) + (size_t)e * KD * NC + c0;

    // A: 128 rows x 32k bf16 = 64B/row; 2 chunks/thread per half
    const __nv_bfloat16 *srcAh[2], *srcAl[2];
    uint32_t adst[2]; int asz[2];
    #pragma unroll
    for (int i = 0; i < 2; i++) {
        int r = (t >> 2) + 64 * i, ca = t & 3;
        int a = s_a[r];
        int row = (a < 0) ? 0 : (WHICH ? a : (a >> 1));
        srcAh[i] = Ahi_b + (size_t)row * KD + ca * 8;
        srcAl[i] = Alo_b + (size_t)row * KD + ca * 8;
        asz[i] = (a < 0) ? 0 : 16;
        adst[i] = r * 64 + ((ca ^ ((r >> 1) & 3)) << 4);
    }
    // B: 32 rows x 256 cols bf16 = 512B/row; 4 chunks/thread per half
    const __nv_bfloat16 *srcBh[4], *srcBl[4];
    uint32_t bdst[4];
    #pragma unroll
    for (int i = 0; i < 4; i++) {
        int u = t + i * 256;
        int r = u >> 5, cb = u & 31;
        srcBh[i] = Whi_b + (size_t)r * NC + cb * 8;
        srcBl[i] = Wlo_b + (size_t)r * NC + cb * 8;
        bdst[i] = r * 512 + ((cb ^ (r & 7)) << 4);
    }

    auto load_stage = [&](int s) {
        uint32_t base = sb + (uint32_t)(s % NSTAGE) * STAGE_BYTES;
        int koff = s * 32;
        size_t bkoff = (size_t)koff * NC;
        #pragma unroll
        for (int i = 0; i < 2; i++) {
            CP_ASYNC16(base + adst[i],          srcAh[i] + koff, asz[i]);
            CP_ASYNC16(base + 8192u + adst[i],  srcAl[i] + koff, asz[i]);
        }
        #pragma unroll
        for (int i = 0; i < 4; i++) {
            CP_ASYNC16(base + 16384u + bdst[i], srcBh[i] + bkoff, 16);
            CP_ASYNC16(base + 32768u + bdst[i], srcBl[i] + bkoff, 16);
        }
        CP_COMMIT();
    };

    // per-lane ldmatrix offsets
    uint32_t aoff[4][2], boff[4][2];
    #pragma unroll
    for (int mi = 0; mi < 4; mi++) {
        int r = wm * 64 + mi * 16 + (lane & 15);
        #pragma unroll
        for (int ks = 0; ks < 2; ks++) {
            int ca = ks * 2 + (lane >> 4);
            aoff[mi][ks] = r * 64 + ((ca ^ ((r >> 1) & 3)) << 4);
        }
    }
    #pragma unroll
    for (int nj = 0; nj < 4; nj++) {
        #pragma unroll
        for (int ks = 0; ks < 2; ks++) {
            int r = ks * 16 + (lane & 15);
            int cb = wn * 8 + nj * 2 + (lane >> 4);
            boff[nj][ks] = r * 512 + ((cb ^ (r & 7)) << 4);
        }
    }

    float acc[4][8][4];
    #pragma unroll
    for (int i = 0; i < 4; i++)
        #pragma unroll
        for (int j = 0; j < 8; j++)
            #pragma unroll
            for (int k = 0; k < 4; k++) acc[i][j][k] = 0.0f;

    load_stage(0);
    load_stage(1);

    for (int s = 0; s < NST; s++) {
        CP_WAIT1();            // stage s arrived (<=1 group outstanding)
        __syncthreads();       // all warps done with stage s-1; see stage s
        if (s + 2 < NST) load_stage(s + 2);
        else CP_COMMIT();      // keep group count aligned
        uint32_t ab = sb + (uint32_t)(s % NSTAGE) * STAGE_BYTES;
        uint32_t bb = ab + 16384u;
        #pragma unroll
        for (int ks = 0; ks < 2; ks++) {
            uint32_t Ah[4][4], Al[4][4];
            #pragma unroll
            for (int mi = 0; mi < 4; mi++) {
                ldsm4(Ah[mi], ab + aoff[mi][ks]);
                ldsm4(Al[mi], ab + 8192u + aoff[mi][ks]);
            }
            #pragma unroll
            for (int nj = 0; nj < 4; nj++) {
                uint32_t Bh[4], Bl[4];
                ldsm4t(Bh, bb + boff[nj][ks]);
                ldsm4t(Bl, bb + 16384u + boff[nj][ks]);
                #pragma unroll
                for (int half = 0; half < 2; half++) {
                    const uint32_t* bh = &Bh[half * 2];
                    const uint32_t* bl = &Bl[half * 2];
                    int n = nj * 2 + half;
                    #pragma unroll
                    for (int mi = 0; mi < 4; mi++) {
                        mma16816(acc[mi][n], Ah[mi], bh);
                        mma16816(acc[mi][n], Ah[mi], bl);
                        mma16816(acc[mi][n], Al[mi], bh);
                    }
                }
            }
        }
    }

    // ---- epilogue ----
    const float* bias_e = bias + (size_t)e * NC + c0;
    int colb = wn * 64 + (lane & 3) * 2;
    float2 bv[8];
    #pragma unroll
    for (int n = 0; n < 8; n++) bv[n] = *(const float2*)(bias_e + colb + n * 8);

    #pragma unroll
    for (int mi = 0; mi < 4; mi++) {
        #pragma unroll
        for (int half = 0; half < 2; half++) {
            int r = wm * 64 + mi * 16 + (lane >> 2) + half * 8;
            int a = s_a[r];
            if (a >= 0) {
                #pragma unroll
                for (int n = 0; n < 8; n++) {
                    float v0 = acc[mi][n][half * 2 + 0] + bv[n].x;
                    float v1 = acc[mi][n][half * 2 + 1] + bv[n].y;
                    size_t col = (size_t)c0 + colb + n * 8;
                    if (WHICH == 0) {
                        v0 = fmaxf(v0, 0.0f); v1 = fmaxf(v1, 0.0f);
                        __nv_bfloat16 h0 = __float2bfloat16(v0);
                        __nv_bfloat16 h1 = __float2bfloat16(v1);
                        size_t o = (size_t)a * HDIM + col;
                        *(uint32_t*)(g_h_hi + o) = pack_bf16x2(v0, v1);
                        *(uint32_t*)(g_h_lo + o) =
                            pack_bf16x2(v0 - __bfloat162float(h0), v1 - __bfloat162float(h1));
                    } else {
                        *(float2*)(g_outb + (size_t)a * DDIM + col) = make_float2(v0, v1);
                    }
                }
            }
        }
    }
}

// ---------------- combine ----------------
__global__ void combine_kernel(float* __restrict__ y) {
    int n = blockIdx.x;
    int t = threadIdx.x;
    float gate0 = g_route_g[2 * n];
    float gate1 = g_route_g[2 * n + 1];
    const float4* o0 = (const float4*)(g_outb + (size_t)(2 * n) * DDIM);
    const float4* o1 = (const float4*)(g_outb + (size_t)(2 * n + 1) * DDIM);
    float4* yp = (float4*)(y + (size_t)n * DDIM);
    float4 a = o0[t], b = o1[t];
    yp[t] = make_float4(gate0 * a.x + gate1 * b.x,
                        gate0 * a.y + gate1 * b.y,
                        gate0 * a.z + gate1 * b.z,
                        gate0 * a.w + gate1 * b.w);
}

// ---------------- launch ----------------
extern "C" void kernel_launch(void* const* d_in, const int* in_sizes, int n_in,
                              void* d_out, int out_size) {
    (void)in_sizes; (void)n_in; (void)out_size;
    const float* x  = (const float*)d_in[0];
    const float* nz = (const float*)d_in[1];
    const float* wg = (const float*)d_in[2];
    const float* wn = (const float*)d_in[3];
    const float* W1 = (const float*)d_in[4];
    const float* b1 = (const float*)d_in[5];
    const float* W2 = (const float*)d_in[6];
    const float* b2 = (const float*)d_in[7];
    float* y = (float*)d_out;

    cudaFuncSetAttribute(moe_gemm_mma<0>, cudaFuncAttributeMaxDynamicSharedMemorySize, GEMM_SMEM);
    cudaFuncSetAttribute(moe_gemm_mma<1>, cudaFuncAttributeMaxDynamicSharedMemorySize, GEMM_SMEM);

    zero_kernel<<<1, 32>>>();
    gate_kernel<<<NTOK / 8, 256>>>(x, nz, wg, wn);
    reduce_kernel<<<NEXP, 256>>>();
    loss_kernel<<<1, 1>>>(y + (size_t)NTOK * DDIM);

    void *xh, *xl, *w1h, *w1l, *w2h, *w2l;
    cudaGetSymbolAddress(&xh, g_x_hi);  cudaGetSymbolAddress(&xl, g_x_lo);
    cudaGetSymbolAddress(&w1h, g_w1_hi); cudaGetSymbolAddress(&w1l, g_w1_lo);
    cudaGetSymbolAddress(&w2h, g_w2_hi); cudaGetSymbolAddress(&w2l, g_w2_lo);

    convert_split<<<1024, 256>>>((const float4*)x, (uint32_t*)xh, (uint32_t*)xl,
                                 (size_t)NTOK * DDIM / 4);
    convert_split<<<4096, 256>>>((const float4*)W1, (uint32_t*)w1h, (uint32_t*)w1l,
                                 (size_t)NEXP * DDIM * HDIM / 4);
    convert_split<<<4096, 256>>>((const float4*)W2, (uint32_t*)w2h, (uint32_t*)w2l,
                                 (size_t)NEXP * HDIM * DDIM / 4);

    moe_gemm_mma<0><<<dim3(HDIM / 256, NASSIGN / 128, NEXP), 256, GEMM_SMEM>>>(b1);
    moe_gemm_mma<1><<<dim3(DDIM / 256, NASSIGN / 128, NEXP), 256, GEMM_SMEM>>>(b2);
    combine_kernel<<<NTOK, 256>>>(y);
}

// round 6
// speedup vs baseline: 3.3873x; 1.2576x over previous
#include <cuda_runtime.h>
#include <cuda_bf16.h>
#include <math.h>
#include <stdint.h>

#define NTOK 8192
#define DDIM 1024
#define HDIM 4096
#define NEXP 8
#define NASSIGN (NTOK*2)

// ---------------- scratch (device globals; no allocation) ----------------
__device__ float g_h[(size_t)NASSIGN * HDIM];      // fp32 hidden
__device__ float g_outb[(size_t)NASSIGN * DDIM];
__device__ float g_loadc[NTOK * NEXP];
__device__ int   g_route_e[NASSIGN];
__device__ float g_route_g[NASSIGN];
__device__ int   g_counts[NEXP];
__device__ int   g_perm[NEXP * NTOK];
__device__ float g_load[NEXP];
__device__ float g_imp[NEXP];
// int8 limbs + scales
__device__ char  g_xq1[(size_t)NTOK * DDIM];
__device__ char  g_xq2[(size_t)NTOK * DDIM];
__device__ float g_sx[NTOK];
__device__ char  g_hq1[(size_t)NASSIGN * HDIM];
__device__ char  g_hq2[(size_t)NASSIGN * HDIM];
__device__ float g_sh[NASSIGN];
// weights transposed to [e][n][k] int8 limbs
__device__ char  g_w1q1[(size_t)NEXP * HDIM * DDIM];
__device__ char  g_w1q2[(size_t)NEXP * HDIM * DDIM];
__device__ float g_sw1[NEXP * HDIM];
__device__ char  g_w2q1[(size_t)NEXP * DDIM * HDIM];
__device__ char  g_w2q2[(size_t)NEXP * DDIM * HDIM];
__device__ float g_sw2[NEXP * DDIM];
__device__ unsigned g_cm1[NEXP * HDIM];   // colmax bits W1
__device__ unsigned g_cm2[NEXP * DDIM];   // colmax bits W2

// ---------------- helpers ----------------
__device__ __forceinline__ uint32_t smem_to_u32(const void* p) {
    uint32_t a;
    asm("{ .reg .u64 t; cvta.to.shared.u64 t, %1; cvt.u32.u64 %0, t; }" : "=r"(a) : "l"(p));
    return a;
}
__device__ __forceinline__ void ldsm4(uint32_t* r, uint32_t a) {
    asm volatile("ldmatrix.sync.aligned.m8n8.x4.shared.b16 {%0,%1,%2,%3}, [%4];"
        : "=r"(r[0]), "=r"(r[1]), "=r"(r[2]), "=r"(r[3]) : "r"(a));
}
__device__ __forceinline__ void imma16832(int* c, const uint32_t* a, const uint32_t* b) {
    asm volatile("mma.sync.aligned.m16n8k32.row.col.s32.s8.s8.s32 "
        "{%0,%1,%2,%3}, {%4,%5,%6,%7}, {%8,%9}, {%0,%1,%2,%3};"
        : "+r"(c[0]), "+r"(c[1]), "+r"(c[2]), "+r"(c[3])
        : "r"(a[0]), "r"(a[1]), "r"(a[2]), "r"(a[3]), "r"(b[0]), "r"(b[1]));
}
#define CP_ASYNC16(dst, src, sz) \
    asm volatile("cp.async.cg.shared.global [%0], [%1], 16, %2;" \
        :: "r"(dst), "l"(src), "r"(sz) : "memory")
#define CP_COMMIT() asm volatile("cp.async.commit_group;" ::: "memory")
#define CP_WAIT2()  asm volatile("cp.async.wait_group 2;" ::: "memory")

// ---------------- zero counters + colmax ----------------
__global__ void zero_all() {
    int i = blockIdx.x * blockDim.x + threadIdx.x;
    if (i < NEXP) g_counts[i] = 0;
    if (i < NEXP * HDIM) g_cm1[i] = 0u;
    if (i < NEXP * DDIM) g_cm2[i] = 0u;
}

// ---------------- gating ----------------
__global__ void gate_kernel(const float* __restrict__ x,
                            const float* __restrict__ noise,
                            const float* __restrict__ wg,
                            const float* __restrict__ wn) {
    int warp = threadIdx.x >> 5;
    int lane = threadIdx.x & 31;
    int n = blockIdx.x * 8 + warp;
    if (n >= NTOK) return;
    float ac[8] = {0,0,0,0,0,0,0,0};
    float an[8] = {0,0,0,0,0,0,0,0};
    const float* xr = x + (size_t)n * DDIM;
    for (int d = lane; d < DDIM; d += 32) {
        float xv = xr[d];
        const float4* wgp = (const float4*)(wg + (size_t)d * 8);
        const float4* wnp = (const float4*)(wn + (size_t)d * 8);
        float4 gA = wgp[0], gB = wgp[1];
        float4 nA = wnp[0], nB = wnp[1];
        ac[0] += xv * gA.x; ac[1] += xv * gA.y; ac[2] += xv * gA.z; ac[3] += xv * gA.w;
        ac[4] += xv * gB.x; ac[5] += xv * gB.y; ac[6] += xv * gB.z; ac[7] += xv * gB.w;
        an[0] += xv * nA.x; an[1] += xv * nA.y; an[2] += xv * nA.z; an[3] += xv * nA.w;
        an[4] += xv * nB.x; an[5] += xv * nB.y; an[6] += xv * nB.z; an[7] += xv * nB.w;
    }
    #pragma unroll
    for (int off = 16; off; off >>= 1)
        #pragma unroll
        for (int e = 0; e < 8; e++) {
            ac[e] += __shfl_xor_sync(0xffffffffu, ac[e], off);
            an[e] += __shfl_xor_sync(0xffffffffu, an[e], off);
        }
    if (lane == 0) {
        float clean[8], sd[8], nz[8];
        #pragma unroll
        for (int e = 0; e < 8; e++) {
            clean[e] = ac[e];
            float z = an[e];
            float sp = fmaxf(z, 0.0f) + log1pf(expf(-fabsf(z)));
            sd[e] = sp + 0.01f;
            nz[e] = clean[e] + noise[(size_t)n * 8 + e] * sd[e];
        }
        int i0 = 0, i1 = -1;
        float v0 = nz[0], v1 = -INFINITY, v2 = -INFINITY;
        #pragma unroll
        for (int e = 1; e < 8; e++) {
            float v = nz[e];
            if (v > v0)      { v2 = v1; v1 = v0; i1 = i0; v0 = v; i0 = e; }
            else if (v > v1) { v2 = v1; v1 = v;  i1 = e; }
            else if (v > v2) { v2 = v; }
        }
        float t = expf(v1 - v0);
        float gate0 = 1.0f / (1.0f + t);
        float gate1 = t / (1.0f + t);
        #pragma unroll
        for (int e = 0; e < 8; e++) {
            bool is_in = nz[e] > v2;
            float thr = is_in ? v2 : v1;
            g_loadc[(size_t)n * 8 + e] = normcdff((clean[e] - thr) / sd[e]);
        }
        g_route_e[2 * n]     = i0;  g_route_g[2 * n]     = gate0;
        g_route_e[2 * n + 1] = i1;  g_route_g[2 * n + 1] = gate1;
        int p0 = atomicAdd(&g_counts[i0], 1);
        g_perm[i0 * NTOK + p0] = 2 * n;
        int p1 = atomicAdd(&g_counts[i1], 1);
        g_perm[i1 * NTOK + p1] = 2 * n + 1;
    }
}

__global__ void reduce_kernel() {
    int e = blockIdx.x;
    int t = threadIdx.x;
    float sl = 0.0f, si = 0.0f;
    for (int n = t; n < NTOK; n += 256) sl += g_loadc[(size_t)n * 8 + e];
    for (int a = t; a < NASSIGN; a += 256)
        if (g_route_e[a] == e) si += g_route_g[a];
    __shared__ float shl[256], shi[256];
    shl[t] = sl; shi[t] = si;
    __syncthreads();
    for (int off = 128; off; off >>= 1) {
        if (t < off) { shl[t] += shl[t + off]; shi[t] += shi[t + off]; }
        __syncthreads();
    }
    if (t == 0) { g_load[e] = shl[0]; g_imp[e] = shi[0]; }
}

__global__ void loss_kernel(float* __restrict__ out) {
    if (threadIdx.x != 0 || blockIdx.x != 0) return;
    float mi = 0.0f, ml = 0.0f;
    for (int e = 0; e < NEXP; e++) { mi += g_imp[e]; ml += g_load[e]; }
    mi *= (1.0f / NEXP); ml *= (1.0f / NEXP);
    float vi = 0.0f, vl = 0.0f;
    for (int e = 0; e < NEXP; e++) {
        float di = g_imp[e] - mi;  vi += di * di;
        float dl = g_load[e] - ml; vl += dl * dl;
    }
    vi *= (1.0f / (NEXP - 1)); vl *= (1.0f / (NEXP - 1));
    out[0] = (vi / (mi * mi + 1e-10f) + vl / (ml * ml + 1e-10f)) * 0.01f;
}

// ---------------- per-row 2-limb int8 quantization ----------------
__global__ void quantize_rows(const float* __restrict__ src,
                              char* __restrict__ q1, char* __restrict__ q2,
                              float* __restrict__ scale, int C) {
    int row = blockIdx.x;
    int t = threadIdx.x;
    const float* r = src + (size_t)row * C;
    float mx = 0.0f;
    for (int i = t; i < C; i += 256) mx = fmaxf(mx, fabsf(r[i]));
    __shared__ float red[256];
    red[t] = mx;
    __syncthreads();
    for (int off = 128; off; off >>= 1) {
        if (t < off) red[t] = fmaxf(red[t], red[t + off]);
        __syncthreads();
    }
    float m = fmaxf(red[0], 1e-20f);
    float s = m * (1.0f / 127.0f);
    float inv = 127.0f / m;
    float inv2 = 254.0f / s;
    if (t == 0) scale[row] = s;
    for (int i = t * 4; i < C; i += 1024) {
        float4 v = *(const float4*)(r + i);
        float a1x = rintf(v.x * inv), a1y = rintf(v.y * inv),
              a1z = rintf(v.z * inv), a1w = rintf(v.w * inv);
        char4 c1 = make_char4((char)(int)a1x, (char)(int)a1y, (char)(int)a1z, (char)(int)a1w);
        char4 c2 = make_char4(
            (char)(int)rintf((v.x - a1x * s) * inv2),
            (char)(int)rintf((v.y - a1y * s) * inv2),
            (char)(int)rintf((v.z - a1z * s) * inv2),
            (char)(int)rintf((v.w - a1w * s) * inv2));
        *(char4*)(q1 + (size_t)row * C + i) = c1;
        *(char4*)(q2 + (size_t)row * C + i) = c2;
    }
}

// ---------------- weight column-max (over k) ----------------
__global__ void colmax_w(const float* __restrict__ W, unsigned* __restrict__ cmax,
                         int K, int N, int seg) {
    int e = blockIdx.z;
    int n = blockIdx.x * 256 + threadIdx.x;
    int k0 = blockIdx.y * seg;
    const float* p = W + ((size_t)e * K + k0) * N + n;
    float mx = 0.0f;
    for (int k = 0; k < seg; k++) mx = fmaxf(mx, fabsf(p[(size_t)k * N]));
    atomicMax(&cmax[(size_t)e * N + n], __float_as_uint(mx));
}

// ---------------- weight quantize + transpose: W[e][k][n] -> q[e][n][k] ----------------
__global__ void quant_w_t(const float* __restrict__ W, const unsigned* __restrict__ cmax,
                          float* __restrict__ swout,
                          char* __restrict__ q1, char* __restrict__ q2, int K, int N) {
    __shared__ float tile[32][33];
    int e = blockIdx.z;
    int k0 = blockIdx.x * 32, n0 = blockIdx.y * 32;
    int tx = threadIdx.x, ty = threadIdx.y;
    const float* Wp = W + (size_t)e * K * N;
    #pragma unroll
    for (int i = 0; i < 4; i++)
        tile[ty + 8 * i][tx] = Wp[(size_t)(k0 + ty + 8 * i) * N + n0 + tx];
    __syncthreads();
    #pragma unroll
    for (int i = 0; i < 4; i++) {
        int n = n0 + ty + 8 * i;
        float v = tile[tx][ty + 8 * i];           // = W[k0+tx][n]
        float m = fmaxf(__uint_as_float(cmax[(size_t)e * N + n]), 1e-20f);
        float s = m * (1.0f / 127.0f);
        float a1 = rintf(v * (127.0f / m));
        float a2 = rintf((v - a1 * s) * (254.0f / s));
        size_t o = ((size_t)e * N + n) * K + k0 + tx;
        q1[o] = (char)(int)a1;
        q2[o] = (char)(int)a2;
        if (blockIdx.x == 0 && tx == 0) swout[(size_t)e * N + n] = s;
    }
}

// ---------------- int8 limb grouped expert GEMM ----------------
// CTA 128x128, k-chunk 64 bytes, 8 warps (2m x 4n), warp tile 64x32, 4-stage pipe.
// Stage: A1@0 (8K) | A2@8192 | B1@16384 | B2@24576 = 32KB.
#define STG 32768
#define NSTAGE 4
#define GEMM_SMEM (NSTAGE * STG)

template <int WHICH>
__global__ __launch_bounds__(256, 1) void moe_gemm_i8(const float* __restrict__ bias) {
    constexpr int KD = WHICH ? HDIM : DDIM;     // k extent (bytes per int8 row)
    constexpr int NC = WHICH ? DDIM : HDIM;
    constexpr int NST = KD / 64;

    const int e = blockIdx.z;
    const int count = g_counts[e];
    const int m0 = blockIdx.y * 128;
    if (m0 >= count) return;
    const int c0 = blockIdx.x * 128;

    extern __shared__ char smem[];
    __shared__ int s_a[128];
    const uint32_t sb = smem_to_u32(smem);
    const int t = threadIdx.x;
    const int lane = t & 31, wid = t >> 5;
    const int wm = wid & 1, wn = wid >> 1;

    if (t < 128) {
        int m = m0 + t;
        s_a[t] = (m < count) ? g_perm[e * NTOK + m] : -1;
    }
    __syncthreads();

    const char* Aq1 = WHICH ? g_hq1 : g_xq1;
    const char* Aq2 = WHICH ? g_hq2 : g_xq2;
    const char* Bq1 = (WHICH ? g_w2q1 : g_w1q1) + ((size_t)e * NC + c0) * KD;
    const char* Bq2 = (WHICH ? g_w2q2 : g_w1q2) + ((size_t)e * NC + c0) * KD;

    // cp.async mapping: 512 16B-chunks per 8KB limb tile, 2 per thread
    const char *sA1[2], *sA2[2];
    uint32_t adst[2]; int asz[2];
    #pragma unroll
    for (int i = 0; i < 2; i++) {
        int u = t + 256 * i;
        int r = u >> 2, c = u & 3;
        int a = s_a[r];
        int rowi = (a < 0) ? 0 : (WHICH ? a : (a >> 1));
        sA1[i] = Aq1 + (size_t)rowi * KD + c * 16;
        sA2[i] = Aq2 + (size_t)rowi * KD + c * 16;
        asz[i] = (a < 0) ? 0 : 16;
        adst[i] = r * 64 + (((uint32_t)(c ^ (r & 3))) << 4);
    }
    const char *sB1[2], *sB2[2];
    uint32_t bdst[2];
    #pragma unroll
    for (int i = 0; i < 2; i++) {
        int u = t + 256 * i;
        int r = u >> 2, c = u & 3;
        sB1[i] = Bq1 + (size_t)r * KD + c * 16;
        sB2[i] = Bq2 + (size_t)r * KD + c * 16;
        bdst[i] = r * 64 + (((uint32_t)(c ^ (r & 3))) << 4);
    }

    auto load_stage = [&](int s) {
        uint32_t base = sb + (uint32_t)(s & (NSTAGE - 1)) * STG;
        int koff = s * 64;
        #pragma unroll
        for (int i = 0; i < 2; i++) {
            CP_ASYNC16(base + adst[i],           sA1[i] + koff, asz[i]);
            CP_ASYNC16(base + 8192u + adst[i],   sA2[i] + koff, asz[i]);
            CP_ASYNC16(base + 16384u + bdst[i],  sB1[i] + koff, 16);
            CP_ASYNC16(base + 24576u + bdst[i],  sB2[i] + koff, 16);
        }
        CP_COMMIT();
    };

    // ldsm base offsets (ks half toggles XOR 32)
    const int g = lane >> 3, r8 = lane & 7;
    uint32_t aoff[4];
    #pragma unroll
    for (int mi = 0; mi < 4; mi++) {
        int row = wm * 64 + mi * 16 + (g & 1) * 8 + r8;
        int c = g >> 1;
        aoff[mi] = row * 64 + (((uint32_t)(c ^ (row & 3))) << 4);
    }
    uint32_t boff[2];
    #pragma unroll
    for (int nj = 0; nj < 2; nj++) {
        int row = wn * 32 + nj * 16 + (g >> 1) * 8 + r8;
        int c = g & 1;
        boff[nj] = 16384u + row * 64 + (((uint32_t)(c ^ (row & 3))) << 4);
    }

    int accM[4][4][4], accC[4][4][4];
    #pragma unroll
    for (int i = 0; i < 4; i++)
        #pragma unroll
        for (int j = 0; j < 4; j++)
            #pragma unroll
            for (int k = 0; k < 4; k++) { accM[i][j][k] = 0; accC[i][j][k] = 0; }

    load_stage(0);
    load_stage(1);
    load_stage(2);

    for (int s = 0; s < NST; s++) {
        CP_WAIT2();
        __syncthreads();
        if (s + 3 < NST) load_stage(s + 3);
        else CP_COMMIT();
        uint32_t ab = sb + (uint32_t)(s & (NSTAGE - 1)) * STG;
        #pragma unroll
        for (int ks = 0; ks < 2; ks++) {
            const uint32_t kx = (uint32_t)ks << 5;
            uint32_t A1f[4][4], A2f[4][4];
            #pragma unroll
            for (int mi = 0; mi < 4; mi++) {
                ldsm4(A1f[mi], ab + (aoff[mi] ^ kx));
                ldsm4(A2f[mi], ab + 8192u + (aoff[mi] ^ kx));
            }
            #pragma unroll
            for (int nj = 0; nj < 2; nj++) {
                uint32_t B1f[4], B2f[4];
                ldsm4(B1f, ab + (boff[nj] ^ kx));
                ldsm4(B2f, ab + 8192u + (boff[nj] ^ kx));
                #pragma unroll
                for (int half = 0; half < 2; half++) {
                    const uint32_t* b1 = &B1f[half * 2];
                    const uint32_t* b2 = &B2f[half * 2];
                    int n = nj * 2 + half;
                    #pragma unroll
                    for (int mi = 0; mi < 4; mi++) {
                        imma16832(accM[mi][n], A1f[mi], b1);
                        imma16832(accC[mi][n], A1f[mi], b2);
                        imma16832(accC[mi][n], A2f[mi], b1);
                    }
                }
            }
        }
    }

    // ---- epilogue ----
    const float* bias_e = bias + (size_t)e * NC + c0;
    const float* sw_e = (WHICH ? g_sw2 : g_sw1) + (size_t)e * NC + c0;
    int colb = wn * 32 + (lane & 3) * 2;
    float2 bv[4], sv[4];
    #pragma unroll
    for (int n = 0; n < 4; n++) {
        bv[n] = *(const float2*)(bias_e + colb + n * 8);
        sv[n] = *(const float2*)(sw_e + colb + n * 8);
    }

    #pragma unroll
    for (int mi = 0; mi < 4; mi++) {
        #pragma unroll
        for (int half = 0; half < 2; half++) {
            int r = wm * 64 + mi * 16 + (lane >> 2) + half * 8;
            int a = s_a[r];
            if (a >= 0) {
                float sa = WHICH ? g_sh[a] : g_sx[a >> 1];
                #pragma unroll
                for (int n = 0; n < 4; n++) {
                    float m0f = (float)accM[mi][n][half * 2 + 0]
                              + (float)accC[mi][n][half * 2 + 0] * (1.0f / 254.0f);
                    float m1f = (float)accM[mi][n][half * 2 + 1]
                              + (float)accC[mi][n][half * 2 + 1] * (1.0f / 254.0f);
                    float v0 = sa * sv[n].x * m0f + bv[n].x;
                    float v1 = sa * sv[n].y * m1f + bv[n].y;
                    size_t col = (size_t)c0 + colb + n * 8;
                    if (WHICH == 0) {
                        v0 = fmaxf(v0, 0.0f); v1 = fmaxf(v1, 0.0f);
                        *(float2*)(g_h + (size_t)a * HDIM + col) = make_float2(v0, v1);
                    } else {
                        *(float2*)(g_outb + (size_t)a * DDIM + col) = make_float2(v0, v1);
                    }
                }
            }
        }
    }
}

// ---------------- combine ----------------
__global__ void combine_kernel(float* __restrict__ y) {
    int n = blockIdx.x;
    int t = threadIdx.x;
    float gate0 = g_route_g[2 * n];
    float gate1 = g_route_g[2 * n + 1];
    const float4* o0 = (const float4*)(g_outb + (size_t)(2 * n) * DDIM);
    const float4* o1 = (const float4*)(g_outb + (size_t)(2 * n + 1) * DDIM);
    float4* yp = (float4*)(y + (size_t)n * DDIM);
    float4 a = o0[t], b = o1[t];
    yp[t] = make_float4(gate0 * a.x + gate1 * b.x,
                        gate0 * a.y + gate1 * b.y,
                        gate0 * a.z + gate1 * b.z,
                        gate0 * a.w + gate1 * b.w);
}

// ---------------- launch ----------------
extern "C" void kernel_launch(void* const* d_in, const int* in_sizes, int n_in,
                              void* d_out, int out_size) {
    (void)in_sizes; (void)n_in; (void)out_size;
    const float* x  = (const float*)d_in[0];
    const float* nz = (const float*)d_in[1];
    const float* wg = (const float*)d_in[2];
    const float* wn = (const float*)d_in[3];
    const float* W1 = (const float*)d_in[4];
    const float* b1 = (const float*)d_in[5];
    const float* W2 = (const float*)d_in[6];
    const float* b2 = (const float*)d_in[7];
    float* y = (float*)d_out;

    cudaFuncSetAttribute(moe_gemm_i8<0>, cudaFuncAttributeMaxDynamicSharedMemorySize, GEMM_SMEM);
    cudaFuncSetAttribute(moe_gemm_i8<1>, cudaFuncAttributeMaxDynamicSharedMemorySize, GEMM_SMEM);

    void *xq1, *xq2, *sx, *hq1, *hq2, *sh, *h;
    void *w1q1, *w1q2, *sw1, *w2q1, *w2q2, *sw2, *cm1, *cm2;
    cudaGetSymbolAddress(&xq1, g_xq1);  cudaGetSymbolAddress(&xq2, g_xq2);
    cudaGetSymbolAddress(&sx, g_sx);    cudaGetSymbolAddress(&h, g_h);
    cudaGetSymbolAddress(&hq1, g_hq1);  cudaGetSymbolAddress(&hq2, g_hq2);
    cudaGetSymbolAddress(&sh, g_sh);
    cudaGetSymbolAddress(&w1q1, g_w1q1); cudaGetSymbolAddress(&w1q2, g_w1q2);
    cudaGetSymbolAddress(&sw1, g_sw1);
    cudaGetSymbolAddress(&w2q1, g_w2q1); cudaGetSymbolAddress(&w2q2, g_w2q2);
    cudaGetSymbolAddress(&sw2, g_sw2);
    cudaGetSymbolAddress(&cm1, g_cm1);  cudaGetSymbolAddress(&cm2, g_cm2);

    zero_all<<<160, 256>>>();
    gate_kernel<<<NTOK / 8, 256>>>(x, nz, wg, wn);
    reduce_kernel<<<NEXP, 256>>>();
    loss_kernel<<<1, 1>>>(y + (size_t)NTOK * DDIM);

    quantize_rows<<<NTOK, 256>>>(x, (char*)xq1, (char*)xq2, (float*)sx, DDIM);
    colmax_w<<<dim3(HDIM / 256, DDIM / 128, NEXP), 256>>>(W1, (unsigned*)cm1, DDIM, HDIM, 128);
    colmax_w<<<dim3(DDIM / 256, HDIM / 128, NEXP), 256>>>(W2, (unsigned*)cm2, HDIM, DDIM, 128);
    quant_w_t<<<dim3(DDIM / 32, HDIM / 32, NEXP), dim3(32, 8)>>>(
        W1, (const unsigned*)cm1, (float*)sw1, (char*)w1q1, (char*)w1q2, DDIM, HDIM);
    quant_w_t<<<dim3(HDIM / 32, DDIM / 32, NEXP), dim3(32, 8)>>>(
        W2, (const unsigned*)cm2, (float*)sw2, (char*)w2q1, (char*)w2q2, HDIM, DDIM);

    moe_gemm_i8<0><<<dim3(HDIM / 128, NASSIGN / 128, NEXP), 256, GEMM_SMEM>>>(b1);
    quantize_rows<<<NASSIGN, 256>>>((const float*)h, (char*)hq1, (char*)hq2, (float*)sh, HDIM);
    moe_gemm_i8<1><<<dim3(DDIM / 128, NASSIGN / 128, NEXP), 256, GEMM_SMEM>>>(b2);
    combine_kernel<<<NTOK, 256>>>(y);
}